// round 4
// baseline (speedup 1.0000x reference)
#include <cuda_runtime.h>

#define NROWS 2048
#define DFEAT 128
#define NT    32
#define TILE  64
#define NTJ   (NROWS / TILE)            // 32 tile rows
#define NBLK  (NTJ * (NTJ + 1) / 2)     // 528 upper-triangular tiles
#define XS    65                        // padded stride, transposed X tiles [d][row]
#define PSR   34                        // row-major P tiles [row][t], even for float2

// dynamic smem layout (bytes)
#define OFF_XJ   0
#define OFF_XK   (DFEAT * XS * 4)                 // 33280
#define OFF_PJ   (OFF_XK + DFEAT * XS * 4)        // 66560
#define OFF_PK   (OFF_PJ + TILE * PSR * 4)        // 75264
#define OFF_RN   (OFF_PK + TILE * PSR * 4)        // 83968  rn[128]
#define OFF_PMIN (OFF_RN + 128 * 4)               // 84480  pmin[128]
#define OFF_PMAX (OFF_PMIN + 128 * 4)             // 84992  pmax[128]
#define SMEM_BYTES (OFF_PMAX + 128 * 4)           // 85504

__device__ double g_acc;
__device__ int    g_count;

__global__ void __launch_bounds__(256, 2)
fused_kernel(const float* __restrict__ X,
             const float* __restrict__ P,
             const float* __restrict__ scale_p,
             const float* __restrict__ target,
             float* __restrict__ out) {
    // ---- triangular decode: blockIdx.x -> (tj, tk), tk >= tj ----
    int idx = blockIdx.x;
    int tj = 0;
    while (idx >= NTJ - tj) { idx -= NTJ - tj; tj++; }
    const int tk = tj + idx;
    const int j0 = tj * TILE;
    const int k0 = tk * TILE;

    extern __shared__ char sm[];
    float* sXj  = (float*)(sm + OFF_XJ);    // [DFEAT][XS] transposed, raw X
    float* sXk  = (float*)(sm + OFF_XK);
    float* sPj  = (float*)(sm + OFF_PJ);    // [TILE][PSR] row-major
    float* sPk  = (float*)(sm + OFF_PK);
    float* rn   = (float*)(sm + OFF_RN);    // [0..63]=j rows, [64..127]=k rows
    float* pmin = (float*)(sm + OFF_PMIN);
    float* pmax = (float*)(sm + OFF_PMAX);
    // list region reuses sXj after the dot phase
    unsigned short* lkey = (unsigned short*)(sm + OFF_XJ);          // <= 4096 * 2B
    float*          lcn  = (float*)(sm + OFF_XJ + 8192);            // <= 4096 * 4B

    __shared__ int   s_cnt;
    __shared__ float s_red[8];
    __shared__ int   s_last;

    const int tid = threadIdx.x;
    const float scale = *scale_p;
    if (tid == 0) s_cnt = 0;

    // ---- load tiles ----
    for (int i = tid; i < TILE * DFEAT; i += 256) {
        int row = i >> 7, d = i & 127;
        sXj[d * XS + row] = X[(size_t)(j0 + row) * DFEAT + d];
        sXk[d * XS + row] = X[(size_t)(k0 + row) * DFEAT + d];
    }
    for (int i = tid; i < TILE * NT; i += 256) {
        int row = i >> 5, t = i & 31;
        sPj[row * PSR + t] = P[(size_t)(j0 + row) * NT + t];
        sPk[row * PSR + t] = P[(size_t)(k0 + row) * NT + t];
    }
    __syncthreads();

    // ---- inline per-row inverse norms (threads 0..127) + pred min/max (128..255) ----
    if (tid < 128) {
        const float* col = (tid < 64) ? (sXj + tid) : (sXk + (tid - 64));
        float s = 0.0f;
        #pragma unroll 16
        for (int d = 0; d < DFEAT; d++) { float v = col[d * XS]; s += v * v; }
        rn[tid] = rsqrtf(s);
    } else {
        int r = tid - 128;
        const float* row = (r < 64) ? (sPj + r * PSR) : (sPk + (r - 64) * PSR);
        float mn = row[0], mx = row[0];
        #pragma unroll
        for (int t = 1; t < NT; t++) {
            float v = row[t];
            mn = fminf(mn, v); mx = fmaxf(mx, v);
        }
        pmin[r] = mn; pmax[r] = mx;
    }
    __syncthreads();

    const int tx = tid & 15;
    const int ty = tid >> 4;

    // ---- dot products (raw X; normalize via rn at the end) ----
    float acc[4][4];
    #pragma unroll
    for (int a = 0; a < 4; a++)
        #pragma unroll
        for (int b = 0; b < 4; b++) acc[a][b] = 0.0f;

    #pragma unroll 8
    for (int d = 0; d < DFEAT; d++) {
        float aj[4], bk[4];
        #pragma unroll
        for (int r = 0; r < 4; r++) {
            aj[r] = sXj[d * XS + ty + 16 * r];
            bk[r] = sXk[d * XS + tx + 16 * r];
        }
        #pragma unroll
        for (int jr = 0; jr < 4; jr++)
            #pragma unroll
            for (int kr = 0; kr < 4; kr++)
                acc[jr][kr] += aj[jr] * bk[kr];
    }

    // ---- thresholds + exact skip bound; gather active pairs ----
    float cneg[4][4];
    int   act[4][4];
    int   nact = 0;
    #pragma unroll
    for (int jr = 0; jr < 4; jr++) {
        int jl = ty + 16 * jr;
        float rnj = rn[jl], pjmn = pmin[jl], pjmx = pmax[jl];
        #pragma unroll
        for (int kr = 0; kr < 4; kr++) {
            int kl = tx + 16 * kr;
            float cosv = acc[jr][kr] * rnj * rn[64 + kl];
            float c = scale * (1.0f - cosv);
            float bound = fmaxf(pjmx - pmin[64 + kl], pmax[64 + kl] - pjmn);
            int valid = (k0 + kl) > (j0 + jl);
            act[jr][kr] = valid && (bound > c);
            cneg[jr][kr] = -c;
            nact += act[jr][kr];
        }
    }
    __syncthreads();   // all sX reads done -> region reusable as list

    int base = atomicAdd(&s_cnt, nact);
    #pragma unroll
    for (int jr = 0; jr < 4; jr++)
        #pragma unroll
        for (int kr = 0; kr < 4; kr++)
            if (act[jr][kr]) {
                int jl = ty + 16 * jr, kl = tx + 16 * kr;
                lkey[base] = (unsigned short)(jl | (kl << 6));
                lcn[base]  = cneg[jr][kr];
                base++;
            }
    __syncthreads();
    const int cnt = s_cnt;

    // ---- hinge over active pairs only ----
    float hsum = 0.0f;
    for (int i = tid; i < cnt; i += 256) {
        unsigned short key = lkey[i];
        int jl = key & 63, kl = key >> 6;
        float cn = lcn[i];
        const float2* pj = (const float2*)(sPj + jl * PSR);
        const float2* pk = (const float2*)(sPk + kl * PSR);
        #pragma unroll
        for (int c2 = 0; c2 < NT / 2; c2++) {
            float2 a = pj[c2], b = pk[c2];
            hsum += fmaxf(fabsf(a.x - b.x) + cn, 0.0f)
                  + fmaxf(fabsf(a.y - b.y) + cn, 0.0f);
        }
    }

    // ---- block reduce + global accumulate ----
    #pragma unroll
    for (int o = 16; o > 0; o >>= 1) hsum += __shfl_xor_sync(0xffffffffu, hsum, o);
    if ((tid & 31) == 0) s_red[tid >> 5] = hsum;
    __syncthreads();
    if (tid == 0) {
        float bs = 0.0f;
        #pragma unroll
        for (int w = 0; w < 8; w++) bs += s_red[w];
        atomicAdd(&g_acc, (double)bs);
        __threadfence();
        int t = atomicAdd(&g_count, 1);
        s_last = (t == NBLK - 1);
    }
    __syncthreads();

    // ---- last block: epilogue + reset for next graph replay ----
    if (s_last && tid == 0) {
        double R  = g_acc;
        double mf = 2.0 * R / ((double)NROWS * (double)(NROWS - 1) * (double)NT);
        out[0] = fmaxf((float)mf - *target, 0.0f);
        g_acc = 0.0;
        g_count = 0;
    }
}

extern "C" void kernel_launch(void* const* d_in, const int* in_sizes, int n_in,
                              void* d_out, int out_size) {
    const float* target = (const float*)d_in[0];
    const float* pred   = (const float*)d_in[1];
    const float* X      = (const float*)d_in[2];
    const float* scale  = (const float*)d_in[4];
    float* out = (float*)d_out;

    cudaFuncSetAttribute(fused_kernel,
                         cudaFuncAttributeMaxDynamicSharedMemorySize, SMEM_BYTES);
    fused_kernel<<<NBLK, 256, SMEM_BYTES>>>(X, pred, scale, target, out);
}

// round 6
// speedup vs baseline: 1.7848x; 1.7848x over previous
#include <cuda_runtime.h>

#define NROWS 2048
#define DFEAT 128
#define NT    32
#define TILE  128
#define NTJ   (NROWS / TILE)            // 16 tile rows
#define NBLK  (NTJ * (NTJ + 1) / 2)     // 136 upper-triangular tiles
#define XS    130                       // row-major X tile stride (floats)
#define PS    34                        // row-major P tile stride (floats)

// dynamic smem layout (bytes)
#define OFF_XJ 0
#define OFF_XK (TILE * XS * 4)                    // 66560
#define OFF_PJ (2 * TILE * XS * 4)                // 133120
#define OFF_PK (OFF_PJ + TILE * PS * 4)           // 150528
#define OFF_RN (OFF_PK + TILE * PS * 4)           // 167936
#define SMEM_BYTES (OFF_RN + 2 * TILE * 4)        // 168960

__device__ double g_acc;
__device__ int    g_count;

// ---- packed f32x2 helpers (sm_103a FFMA2 / FADD2) ----
typedef unsigned long long u64t;

__device__ __forceinline__ u64t pack2(float lo, float hi) {
    u64t u; asm("mov.b64 %0, {%1, %2};" : "=l"(u) : "f"(lo), "f"(hi)); return u;
}
__device__ __forceinline__ void unpack2(u64t u, float& lo, float& hi) {
    asm("mov.b64 {%0, %1}, %2;" : "=f"(lo), "=f"(hi) : "l"(u));
}
__device__ __forceinline__ u64t fma2(u64t a, u64t b, u64t c) {
    u64t d; asm("fma.rn.f32x2 %0, %1, %2, %3;" : "=l"(d) : "l"(a), "l"(b), "l"(c)); return d;
}
__device__ __forceinline__ u64t add2(u64t a, u64t b) {
    u64t d; asm("add.rn.f32x2 %0, %1, %2;" : "=l"(d) : "l"(a), "l"(b)); return d;
}
__device__ __forceinline__ u64t lds2(const float* p) {
    float2 v = *reinterpret_cast<const float2*>(p);
    return pack2(v.x, v.y);
}

__global__ void __launch_bounds__(256, 1)
fused_kernel(const float* __restrict__ X,
             const float* __restrict__ P,
             const float* __restrict__ scale_p,
             const float* __restrict__ target,
             float* __restrict__ out) {
    // ---- triangular decode: blockIdx.x -> (tj, tk), tk >= tj ----
    int idx = blockIdx.x;
    int tj = 0;
    while (idx >= NTJ - tj) { idx -= NTJ - tj; tj++; }
    const int tk = tj + idx;
    const int j0 = tj * TILE;
    const int k0 = tk * TILE;

    extern __shared__ char sm[];
    float* sXj = (float*)(sm + OFF_XJ);   // [TILE][XS] row-major, raw X
    float* sXk = (float*)(sm + OFF_XK);
    float* sPj = (float*)(sm + OFF_PJ);   // [TILE][PS] row-major
    float* sPk = (float*)(sm + OFF_PK);   // NEGATED pk values
    float* rn  = (float*)(sm + OFF_RN);   // [0..127]=j rows, [128..255]=k rows

    __shared__ float s_red[8];
    __shared__ int   s_last;

    const int tid = threadIdx.x;
    const float scale = *scale_p;

    // ---- load X tiles (float4 gmem -> 2x float2 smem, row-major) ----
    for (int i = tid; i < TILE * DFEAT / 4; i += 256) {
        int row = i >> 5;          // 32 float4 per row
        int c4  = (i & 31) * 4;
        float4 vj = *(const float4*)(X + (size_t)(j0 + row) * DFEAT + c4);
        float4 vk = *(const float4*)(X + (size_t)(k0 + row) * DFEAT + c4);
        *(float2*)(sXj + row * XS + c4)     = make_float2(vj.x, vj.y);
        *(float2*)(sXj + row * XS + c4 + 2) = make_float2(vj.z, vj.w);
        *(float2*)(sXk + row * XS + c4)     = make_float2(vk.x, vk.y);
        *(float2*)(sXk + row * XS + c4 + 2) = make_float2(vk.z, vk.w);
    }
    // ---- load P tiles; k tile stored NEGATED so diff = add2(pj, nk) ----
    for (int i = tid; i < TILE * NT / 4; i += 256) {
        int row = i >> 3;          // 8 float4 per row
        int c4  = (i & 7) * 4;
        float4 vj = *(const float4*)(P + (size_t)(j0 + row) * NT + c4);
        float4 vk = *(const float4*)(P + (size_t)(k0 + row) * NT + c4);
        *(float2*)(sPj + row * PS + c4)     = make_float2(vj.x, vj.y);
        *(float2*)(sPj + row * PS + c4 + 2) = make_float2(vj.z, vj.w);
        *(float2*)(sPk + row * PS + c4)     = make_float2(-vk.x, -vk.y);
        *(float2*)(sPk + row * PS + c4 + 2) = make_float2(-vk.z, -vk.w);
    }
    __syncthreads();

    // ---- inline per-row inverse norms: one row per thread ----
    {
        const float* rowp = (tid < 128) ? (sXj + tid * XS) : (sXk + (tid - 128) * XS);
        float s = 0.0f;
        #pragma unroll 16
        for (int d = 0; d < DFEAT; d += 2) {
            float2 v = *(const float2*)(rowp + d);
            s += v.x * v.x + v.y * v.y;
        }
        rn[tid] = rsqrtf(s);
    }
    __syncthreads();

    const int tx = tid & 15;
    const int ty = tid >> 4;

    // ---- dot products: 8x8 register tile, packed f32x2 over d ----
    u64t acc2[8][8];
    #pragma unroll
    for (int r = 0; r < 8; r++)
        #pragma unroll
        for (int s = 0; s < 8; s++) acc2[r][s] = 0ULL;

    const float* xjb = sXj + ty * XS;
    const float* xkb = sXk + tx * XS;
    #pragma unroll 4
    for (int d2 = 0; d2 < DFEAT / 2; d2++) {
        u64t aj[8], bk[8];
        #pragma unroll
        for (int r = 0; r < 8; r++) aj[r] = lds2(xjb + (16 * r) * XS + 2 * d2);
        #pragma unroll
        for (int s = 0; s < 8; s++) bk[s] = lds2(xkb + (16 * s) * XS + 2 * d2);
        #pragma unroll
        for (int r = 0; r < 8; r++)
            #pragma unroll
            for (int s = 0; s < 8; s++)
                acc2[r][s] = fma2(aj[r], bk[s], acc2[r][s]);
    }

    // ---- thresholds: cn = -scale*(1 - cos) ; invalid (k<=j) pairs get -inf ----
    float cn[8][8];
    #pragma unroll
    for (int r = 0; r < 8; r++) {
        int jl = ty + 16 * r;
        float rnj = rn[jl];
        #pragma unroll
        for (int s = 0; s < 8; s++) {
            int kl = tx + 16 * s;
            float lo, hi; unpack2(acc2[r][s], lo, hi);
            float cosv = (lo + hi) * rnj * rn[128 + kl];
            float c = scale * cosv - scale;               // = -scale*(1-cos)
            cn[r][s] = ((k0 + kl) > (j0 + jl)) ? c : -1.0e30f;
        }
    }

    // ---- hinge: packed diff + packed accumulate, |x| as FADD modifier ----
    u64t hs2[8];
    #pragma unroll
    for (int s = 0; s < 8; s++) hs2[s] = 0ULL;

    const float* pjb = sPj + ty * PS;
    const float* pkb = sPk + tx * PS;
    #pragma unroll 1
    for (int t2 = 0; t2 < NT / 2; t2++) {
        u64t pj[8], nk[8];
        #pragma unroll
        for (int r = 0; r < 8; r++) pj[r] = lds2(pjb + (16 * r) * PS + 2 * t2);
        #pragma unroll
        for (int s = 0; s < 8; s++) nk[s] = lds2(pkb + (16 * s) * PS + 2 * t2);
        #pragma unroll
        for (int r = 0; r < 8; r++)
            #pragma unroll
            for (int s = 0; s < 8; s++) {
                u64t d2v = add2(pj[r], nk[s]);            // {pj-pk} x2 (FADD2)
                float lo, hi; unpack2(d2v, lo, hi);
                float tl = fabsf(lo) + cn[r][s];          // FADD |src| modifier
                float th = fabsf(hi) + cn[r][s];
                tl = fmaxf(tl, 0.0f);                     // FMNMX (alu pipe)
                th = fmaxf(th, 0.0f);
                hs2[s] = add2(hs2[s], pack2(tl, th));     // FADD2 accumulate
            }
    }

    float hsum = 0.0f;
    #pragma unroll
    for (int s = 0; s < 8; s++) {
        float lo, hi; unpack2(hs2[s], lo, hi);
        hsum += lo + hi;
    }

    // ---- block reduce + global accumulate ----
    #pragma unroll
    for (int o = 16; o > 0; o >>= 1) hsum += __shfl_xor_sync(0xffffffffu, hsum, o);
    if ((tid & 31) == 0) s_red[tid >> 5] = hsum;
    __syncthreads();
    if (tid == 0) {
        float bs = 0.0f;
        #pragma unroll
        for (int w = 0; w < 8; w++) bs += s_red[w];
        atomicAdd(&g_acc, (double)bs);
        __threadfence();
        int t = atomicAdd(&g_count, 1);
        s_last = (t == NBLK - 1);
    }
    __syncthreads();

    // ---- last block: epilogue + reset for next graph replay ----
    if (s_last && tid == 0) {
        double R  = g_acc;
        double mf = 2.0 * R / ((double)NROWS * (double)(NROWS - 1) * (double)NT);
        out[0] = fmaxf((float)mf - *target, 0.0f);
        g_acc = 0.0;
        g_count = 0;
    }
}

extern "C" void kernel_launch(void* const* d_in, const int* in_sizes, int n_in,
                              void* d_out, int out_size) {
    const float* target = (const float*)d_in[0];
    const float* pred   = (const float*)d_in[1];
    const float* X      = (const float*)d_in[2];
    const float* scale  = (const float*)d_in[4];
    float* out = (float*)d_out;

    cudaFuncSetAttribute(fused_kernel,
                         cudaFuncAttributeMaxDynamicSharedMemorySize, SMEM_BYTES);
    fused_kernel<<<NBLK, 256, SMEM_BYTES>>>(X, pred, scale, target, out);
}

// round 7
// speedup vs baseline: 1.8089x; 1.0135x over previous
#include <cuda_runtime.h>

#define NROWS 2048
#define DFEAT 128
#define NT    32
#define TILE  128
#define NTJ   (NROWS / TILE)            // 16 tile rows
#define NBLK  (NTJ * (NTJ + 1) / 2)     // 136 upper-triangular tiles
#define XS    130                       // row-major X tile stride (floats)
#define PS    34                        // row-major P tile stride (floats)
#define NTHR  512

// dynamic smem layout (bytes)
#define OFF_XJ 0
#define OFF_XK (TILE * XS * 4)                    // 66560
#define OFF_PJ (2 * TILE * XS * 4)                // 133120
#define OFF_PK (OFF_PJ + TILE * PS * 4)           // 150528
#define OFF_RN (OFF_PK + TILE * PS * 4)           // 167936
#define SMEM_BYTES (OFF_RN + 2 * TILE * 4)        // 168960

__device__ double g_acc;
__device__ int    g_count;

// ---- packed f32x2 helpers (sm_103a FFMA2 / FADD2) ----
typedef unsigned long long u64t;

__device__ __forceinline__ u64t pack2(float lo, float hi) {
    u64t u; asm("mov.b64 %0, {%1, %2};" : "=l"(u) : "f"(lo), "f"(hi)); return u;
}
__device__ __forceinline__ void unpack2(u64t u, float& lo, float& hi) {
    asm("mov.b64 {%0, %1}, %2;" : "=f"(lo), "=f"(hi) : "l"(u));
}
__device__ __forceinline__ u64t fma2(u64t a, u64t b, u64t c) {
    u64t d; asm("fma.rn.f32x2 %0, %1, %2, %3;" : "=l"(d) : "l"(a), "l"(b), "l"(c)); return d;
}
__device__ __forceinline__ u64t add2(u64t a, u64t b) {
    u64t d; asm("add.rn.f32x2 %0, %1, %2;" : "=l"(d) : "l"(a), "l"(b)); return d;
}
__device__ __forceinline__ u64t lds2(const float* p) {
    float2 v = *reinterpret_cast<const float2*>(p);
    return pack2(v.x, v.y);
}

__global__ void __launch_bounds__(NTHR, 1)
fused_kernel(const float* __restrict__ X,
             const float* __restrict__ P,
             const float* __restrict__ scale_p,
             const float* __restrict__ target,
             float* __restrict__ out) {
    // ---- triangular decode: blockIdx.x -> (tj, tk), tk >= tj ----
    int idx = blockIdx.x;
    int tj = 0;
    while (idx >= NTJ - tj) { idx -= NTJ - tj; tj++; }
    const int tk = tj + idx;
    const int j0 = tj * TILE;
    const int k0 = tk * TILE;

    extern __shared__ char sm[];
    float* sXj = (float*)(sm + OFF_XJ);   // [TILE][XS] row-major, raw X
    float* sXk = (float*)(sm + OFF_XK);
    float* sPj = (float*)(sm + OFF_PJ);   // [TILE][PS] row-major
    float* sPk = (float*)(sm + OFF_PK);   // NEGATED pk values
    float* rn  = (float*)(sm + OFF_RN);   // [0..127]=j rows, [128..255]=k rows

    __shared__ float s_red[16];
    __shared__ int   s_last;

    const int tid = threadIdx.x;
    const float scale = *scale_p;

    // ---- load X tiles (float4 gmem -> 2x float2 smem, row-major) ----
    for (int i = tid; i < TILE * DFEAT / 4; i += NTHR) {
        int row = i >> 5;          // 32 float4 per row
        int c4  = (i & 31) * 4;
        float4 vj = *(const float4*)(X + (size_t)(j0 + row) * DFEAT + c4);
        float4 vk = *(const float4*)(X + (size_t)(k0 + row) * DFEAT + c4);
        *(float2*)(sXj + row * XS + c4)     = make_float2(vj.x, vj.y);
        *(float2*)(sXj + row * XS + c4 + 2) = make_float2(vj.z, vj.w);
        *(float2*)(sXk + row * XS + c4)     = make_float2(vk.x, vk.y);
        *(float2*)(sXk + row * XS + c4 + 2) = make_float2(vk.z, vk.w);
    }
    // ---- load P tiles; k tile stored NEGATED so diff = add2(pj, nk) ----
    for (int i = tid; i < TILE * NT / 4; i += NTHR) {
        int row = i >> 3;          // 8 float4 per row
        int c4  = (i & 7) * 4;
        float4 vj = *(const float4*)(P + (size_t)(j0 + row) * NT + c4);
        float4 vk = *(const float4*)(P + (size_t)(k0 + row) * NT + c4);
        *(float2*)(sPj + row * PS + c4)     = make_float2(vj.x, vj.y);
        *(float2*)(sPj + row * PS + c4 + 2) = make_float2(vj.z, vj.w);
        *(float2*)(sPk + row * PS + c4)     = make_float2(-vk.x, -vk.y);
        *(float2*)(sPk + row * PS + c4 + 2) = make_float2(-vk.z, -vk.w);
    }
    __syncthreads();

    // ---- inline per-row inverse norms: threads 0..255, one row each ----
    if (tid < 256) {
        const float* rowp = (tid < 128) ? (sXj + tid * XS) : (sXk + (tid - 128) * XS);
        float s = 0.0f;
        #pragma unroll 16
        for (int d = 0; d < DFEAT; d += 2) {
            float2 v = *(const float2*)(rowp + d);
            s += v.x * v.x + v.y * v.y;
        }
        rn[tid] = rsqrtf(s);
    }
    __syncthreads();

    const int tx = tid & 15;       // kl = tx + 16*s, s in [0,8)
    const int ty = tid >> 4;       // jl = ty + 32*r, r in [0,4)

    // ---- dot products: 4x8 register tile, packed f32x2 over d ----
    u64t acc2[4][8];
    #pragma unroll
    for (int r = 0; r < 4; r++)
        #pragma unroll
        for (int s = 0; s < 8; s++) acc2[r][s] = 0ULL;

    const float* xjb = sXj + ty * XS;
    const float* xkb = sXk + tx * XS;
    #pragma unroll 4
    for (int d2 = 0; d2 < DFEAT / 2; d2++) {
        u64t aj[4], bk[8];
        #pragma unroll
        for (int r = 0; r < 4; r++) aj[r] = lds2(xjb + (32 * r) * XS + 2 * d2);
        #pragma unroll
        for (int s = 0; s < 8; s++) bk[s] = lds2(xkb + (16 * s) * XS + 2 * d2);
        #pragma unroll
        for (int r = 0; r < 4; r++)
            #pragma unroll
            for (int s = 0; s < 8; s++)
                acc2[r][s] = fma2(aj[r], bk[s], acc2[r][s]);
    }

    // ---- thresholds: cn = -scale*(1 - cos) ; invalid (k<=j) pairs get -inf ----
    float cn[4][8];
    #pragma unroll
    for (int r = 0; r < 4; r++) {
        int jl = ty + 32 * r;
        float rnj = rn[jl];
        #pragma unroll
        for (int s = 0; s < 8; s++) {
            int kl = tx + 16 * s;
            float lo, hi; unpack2(acc2[r][s], lo, hi);
            float cosv = (lo + hi) * rnj * rn[128 + kl];
            float c = scale * cosv - scale;               // = -scale*(1-cos)
            cn[r][s] = ((k0 + kl) > (j0 + jl)) ? c : -1.0e30f;
        }
    }

    // ---- hinge: packed diff + packed accumulate, |x| as FADD modifier ----
    u64t hs2[8];
    #pragma unroll
    for (int s = 0; s < 8; s++) hs2[s] = 0ULL;

    const float* pjb = sPj + ty * PS;
    const float* pkb = sPk + tx * PS;
    #pragma unroll 2
    for (int t2 = 0; t2 < NT / 2; t2++) {
        u64t pj[4], nk[8];
        #pragma unroll
        for (int r = 0; r < 4; r++) pj[r] = lds2(pjb + (32 * r) * PS + 2 * t2);
        #pragma unroll
        for (int s = 0; s < 8; s++) nk[s] = lds2(pkb + (16 * s) * PS + 2 * t2);
        #pragma unroll
        for (int r = 0; r < 4; r++)
            #pragma unroll
            for (int s = 0; s < 8; s++) {
                u64t d2v = add2(pj[r], nk[s]);            // {pj-pk} x2 (FADD2)
                float lo, hi; unpack2(d2v, lo, hi);
                float tl = fabsf(lo) + cn[r][s];          // FADD |src| modifier
                float th = fabsf(hi) + cn[r][s];
                tl = fmaxf(tl, 0.0f);                     // FMNMX (alu pipe)
                th = fmaxf(th, 0.0f);
                hs2[s] = add2(hs2[s], pack2(tl, th));     // FADD2 accumulate
            }
    }

    float hsum = 0.0f;
    #pragma unroll
    for (int s = 0; s < 8; s++) {
        float lo, hi; unpack2(hs2[s], lo, hi);
        hsum += lo + hi;
    }

    // ---- block reduce + global accumulate ----
    #pragma unroll
    for (int o = 16; o > 0; o >>= 1) hsum += __shfl_xor_sync(0xffffffffu, hsum, o);
    if ((tid & 31) == 0) s_red[tid >> 5] = hsum;
    __syncthreads();
    if (tid == 0) {
        float bs = 0.0f;
        #pragma unroll
        for (int w = 0; w < NTHR / 32; w++) bs += s_red[w];
        atomicAdd(&g_acc, (double)bs);
        __threadfence();
        int t = atomicAdd(&g_count, 1);
        s_last = (t == NBLK - 1);
    }
    __syncthreads();

    // ---- last block: epilogue + reset for next graph replay ----
    if (s_last && tid == 0) {
        double R  = g_acc;
        double mf = 2.0 * R / ((double)NROWS * (double)(NROWS - 1) * (double)NT);
        out[0] = fmaxf((float)mf - *target, 0.0f);
        g_acc = 0.0;
        g_count = 0;
    }
}

extern "C" void kernel_launch(void* const* d_in, const int* in_sizes, int n_in,
                              void* d_out, int out_size) {
    const float* target = (const float*)d_in[0];
    const float* pred   = (const float*)d_in[1];
    const float* X      = (const float*)d_in[2];
    const float* scale  = (const float*)d_in[4];
    float* out = (float*)d_out;

    cudaFuncSetAttribute(fused_kernel,
                         cudaFuncAttributeMaxDynamicSharedMemorySize, SMEM_BYTES);
    fused_kernel<<<NBLK, NTHR, SMEM_BYTES>>>(X, pred, scale, target, out);
}

// round 12
// speedup vs baseline: 1.8127x; 1.0021x over previous
#include <cuda_runtime.h>
#include <cuda_bf16.h>
#include <cstdint>

#define NROWS 2048
#define DFEAT 128
#define NT    32
#define TILE  128
#define NTJ   (NROWS / TILE)            // 16
#define NBLK  (NTJ * (NTJ + 1) / 2)     // 136 upper-triangular tiles
#define PS    34                        // P tile row stride (floats)
#define NTHR  512
#define CNS   129                       // cn tile stride (floats)
#define XSB   136                       // bf16 tile row stride (elements) -> 272B

// smem layout (bytes): 4 bf16 tiles [128][136] (34816B each)
#define OFF_AH 0
#define OFF_AL 34816
#define OFF_BH 69632
#define OFF_BL 104448
#define OFF_PJ 139264                   // [TILE][PS] f32
#define OFF_PK (OFF_PJ + TILE * PS * 4) // 156672
#define OFF_RN (OFF_PK + TILE * PS * 4) // 174080, rn[256]
#define SMEM_BYTES (OFF_RN + 256 * 4)   // 175104
// cn overlays AH+AL after MMA: 128*129*4 = 66048 <= 69632

__device__ double g_acc;
__device__ int    g_count;

// ---------------- packed f32x2 helpers ----------------
typedef unsigned long long u64t;
__device__ __forceinline__ u64t pack2(float lo, float hi) {
    u64t u; asm("mov.b64 %0, {%1, %2};" : "=l"(u) : "f"(lo), "f"(hi)); return u;
}
__device__ __forceinline__ void unpack2(u64t u, float& lo, float& hi) {
    asm("mov.b64 {%0, %1}, %2;" : "=f"(lo), "=f"(hi) : "l"(u));
}
__device__ __forceinline__ u64t add2(u64t a, u64t b) {
    u64t d; asm("add.rn.f32x2 %0, %1, %2;" : "=l"(d) : "l"(a), "l"(b)); return d;
}
__device__ __forceinline__ u64t lds2(const float* p) {
    float2 v = *reinterpret_cast<const float2*>(p);
    return pack2(v.x, v.y);
}

// ---------------- warp-MMA helpers (sm_80+ PTX, works at compute_103) ------
__device__ __forceinline__ uint32_t smem_u32(const void* p) {
    uint32_t a;
    asm("{ .reg .u64 t; cvta.to.shared.u64 t, %1; cvt.u32.u64 %0, t; }" : "=r"(a) : "l"(p));
    return a;
}
__device__ __forceinline__ void ldsm4(uint32_t addr, uint32_t& r0, uint32_t& r1,
                                      uint32_t& r2, uint32_t& r3) {
    asm volatile("ldmatrix.sync.aligned.m8n8.x4.shared.b16 {%0,%1,%2,%3}, [%4];"
                 : "=r"(r0), "=r"(r1), "=r"(r2), "=r"(r3) : "r"(addr));
}
__device__ __forceinline__ void mma16816(float* d, const uint32_t* a,
                                         uint32_t b0, uint32_t b1) {
    asm volatile(
        "mma.sync.aligned.m16n8k16.row.col.f32.bf16.bf16.f32 "
        "{%0,%1,%2,%3}, {%4,%5,%6,%7}, {%8,%9}, {%0,%1,%2,%3};"
        : "+f"(d[0]), "+f"(d[1]), "+f"(d[2]), "+f"(d[3])
        : "r"(a[0]), "r"(a[1]), "r"(a[2]), "r"(a[3]), "r"(b0), "r"(b1));
}
__device__ __forceinline__ unsigned pack_bf16x2(float lo, float hi) {
    unsigned r; asm("cvt.rn.bf16x2.f32 %0, %1, %2;" : "=r"(r) : "f"(hi), "f"(lo)); return r;
}

__global__ void __launch_bounds__(NTHR, 1)
fused_kernel(const float* __restrict__ X,
             const float* __restrict__ P,
             const float* __restrict__ scale_p,
             const float* __restrict__ target,
             float* __restrict__ out) {
    // ---- triangular decode ----
    int idx = blockIdx.x;
    int tj = 0;
    while (idx >= NTJ - tj) { idx -= NTJ - tj; tj++; }
    const int tk = tj + idx;
    const int j0 = tj * TILE;
    const int k0 = tk * TILE;

    extern __shared__ char sm[];
    float* sPj = (float*)(sm + OFF_PJ);
    float* sPk = (float*)(sm + OFF_PK);   // negated
    float* rn  = (float*)(sm + OFF_RN);
    float* cn  = (float*)(sm + 0);        // overlays A tiles post-MMA
    const uint32_t sbase = smem_u32(sm);

    __shared__ float s_red[16];
    __shared__ int   s_last;

    const int tid  = threadIdx.x;
    const int wid  = tid >> 5;
    const int lane = tid & 31;
    const float scale = *scale_p;

    // ---- X tiles: fp32 -> (bf16 hi, bf16 lo) split, padded-stride layout ----
    for (int i = tid; i < 2 * TILE * DFEAT / 4; i += NTHR) {
        int tile = i >> 12;                  // 0 = J(A), 1 = K(B)
        int rem  = i & 4095;
        int row  = rem >> 5;
        int c4   = (rem & 31) * 4;
        int g0   = tile ? k0 : j0;
        float4 v = *(const float4*)(X + (size_t)(g0 + row) * DFEAT + c4);
        unsigned hw0 = pack_bf16x2(v.x, v.y);
        unsigned hw1 = pack_bf16x2(v.z, v.w);
        float r0 = v.x - __uint_as_float(hw0 << 16);
        float r1 = v.y - __uint_as_float(hw0 & 0xffff0000u);
        float r2 = v.z - __uint_as_float(hw1 << 16);
        float r3 = v.w - __uint_as_float(hw1 & 0xffff0000u);
        unsigned lw0 = pack_bf16x2(r0, r1);
        unsigned lw1 = pack_bf16x2(r2, r3);
        uint32_t o = (uint32_t)(row * XSB + c4) * 2;
        char* hbase = sm + (tile ? OFF_BH : OFF_AH);
        char* lbase = sm + (tile ? OFF_BL : OFF_AL);
        *(uint2*)(hbase + o) = make_uint2(hw0, hw1);
        *(uint2*)(lbase + o) = make_uint2(lw0, lw1);
    }
    // ---- P tiles (k negated) ----
    for (int i = tid; i < TILE * NT / 4; i += NTHR) {
        int row = i >> 3;
        int c4  = (i & 7) * 4;
        float4 vj = *(const float4*)(P + (size_t)(j0 + row) * NT + c4);
        float4 vk = *(const float4*)(P + (size_t)(k0 + row) * NT + c4);
        *(float2*)(sPj + row * PS + c4)     = make_float2(vj.x, vj.y);
        *(float2*)(sPj + row * PS + c4 + 2) = make_float2(vj.z, vj.w);
        *(float2*)(sPk + row * PS + c4)     = make_float2(-vk.x, -vk.y);
        *(float2*)(sPk + row * PS + c4 + 2) = make_float2(-vk.z, -vk.w);
    }
    // ---- inverse norms from gmem (f32 exact) ----
    if (tid < 256) {
        int g0 = (tid < 128) ? (j0 + tid) : (k0 + tid - 128);
        const float4* rp = (const float4*)(X + (size_t)g0 * DFEAT);
        float s = 0.0f;
        #pragma unroll 8
        for (int q = 0; q < 32; q++) {
            float4 v = rp[q];
            s += v.x * v.x + v.y * v.y + v.z * v.z + v.w * v.w;
        }
        rn[tid] = rsqrtf(s);
    }
    __syncthreads();

    // ---- warp MMA: each warp computes 32x32 Gram sub-tile ----
    // acc layout: [mt][nt][reg]; m = m0+mt*16+(lane>>2)+8*(reg>>1),
    //                            n = n0+nt*8 +(lane&3)*2+(reg&1)
    const int m0 = (wid & 3) * 32;
    const int n0 = (wid >> 2) * 32;
    float acc[2][4][4];
    #pragma unroll
    for (int mt = 0; mt < 2; mt++)
        #pragma unroll
        for (int nt = 0; nt < 4; nt++)
            #pragma unroll
            for (int q = 0; q < 4; q++) acc[mt][nt][q] = 0.0f;

    // ldmatrix lane addressing (byte offsets within a bf16 tile)
    // A (m16k16, x4): row = m0+mt*16+(lane&15), colchunk = (lane>>4)*8 + kk*16
    const uint32_t aRow = (uint32_t)(m0 + (lane & 15));
    const uint32_t aCol0 = (uint32_t)((lane >> 4) * 8);
    // B (two n8k16 tiles, x4): row = n0+nth*16+(lane&7)+(lane>>4)*8,
    //                          colchunk = ((lane>>3)&1)*8 + kk*16
    const uint32_t bRow = (uint32_t)(n0 + (lane & 7) + (lane >> 4) * 8);
    const uint32_t bCol0 = (uint32_t)(((lane >> 3) & 1) * 8);

    #pragma unroll
    for (int pass = 0; pass < 3; pass++) {
        const uint32_t aBase = sbase + (pass == 2 ? OFF_AL : OFF_AH);
        const uint32_t bBase = sbase + (pass == 1 ? OFF_BL : OFF_BH);
        #pragma unroll
        for (int kk = 0; kk < 8; kk++) {
            uint32_t a[2][4];
            #pragma unroll
            for (int mt = 0; mt < 2; mt++) {
                uint32_t ad = aBase + ((aRow + mt * 16) * XSB + aCol0 + kk * 16) * 2;
                ldsm4(ad, a[mt][0], a[mt][1], a[mt][2], a[mt][3]);
            }
            uint32_t b[2][4];
            #pragma unroll
            for (int nth = 0; nth < 2; nth++) {
                uint32_t bd = bBase + ((bRow + nth * 16) * XSB + bCol0 + kk * 16) * 2;
                ldsm4(bd, b[nth][0], b[nth][1], b[nth][2], b[nth][3]);
            }
            #pragma unroll
            for (int mt = 0; mt < 2; mt++)
                #pragma unroll
                for (int nt = 0; nt < 4; nt++)
                    mma16816(acc[mt][nt], a[mt], b[nt >> 1][(nt & 1) * 2],
                             b[nt >> 1][(nt & 1) * 2 + 1]);
        }
    }
    __syncthreads();   // all ldmatrix reads done -> A region reusable as cn

    // ---- fold norms + scale, stage cn[m][n] to smem ----
    {
        const int g = lane >> 2;
        const int q = lane & 3;
        float rnj[2][2], rnk[4][2];
        #pragma unroll
        for (int mt = 0; mt < 2; mt++)
            #pragma unroll
            for (int h = 0; h < 2; h++)
                rnj[mt][h] = rn[m0 + mt * 16 + 8 * h + g];
        #pragma unroll
        for (int nt = 0; nt < 4; nt++)
            #pragma unroll
            for (int p = 0; p < 2; p++)
                rnk[nt][p] = rn[128 + n0 + nt * 8 + q * 2 + p];
        #pragma unroll
        for (int mt = 0; mt < 2; mt++)
            #pragma unroll
            for (int nt = 0; nt < 4; nt++)
                #pragma unroll
                for (int r = 0; r < 4; r++) {
                    int m = m0 + mt * 16 + 8 * (r >> 1) + g;
                    int n = n0 + nt * 8 + q * 2 + (r & 1);
                    float cosv = acc[mt][nt][r] * rnj[mt][r >> 1] * rnk[nt][r & 1];
                    float v = scale * cosv - scale;           // -scale*(1-cos)
                    cn[m * CNS + n] = ((k0 + n) > (j0 + m)) ? v : -1.0e30f;
                }
    }
    __syncthreads();

    // ---- hinge: 4x8 register tile, packed f32x2 (R7) ----
    const int tx = tid & 15;
    const int ty = tid >> 4;

    float cnr[4][8];
    #pragma unroll
    for (int r = 0; r < 4; r++)
        #pragma unroll
        for (int s = 0; s < 8; s++)
            cnr[r][s] = cn[(ty + 32 * r) * CNS + tx + 16 * s];

    u64t hs2[8];
    #pragma unroll
    for (int s = 0; s < 8; s++) hs2[s] = 0ULL;

    const float* pjb = sPj + ty * PS;
    const float* pkb = sPk + tx * PS;
    #pragma unroll 2
    for (int t2 = 0; t2 < NT / 2; t2++) {
        u64t pj[4], nk[8];
        #pragma unroll
        for (int r = 0; r < 4; r++) pj[r] = lds2(pjb + (32 * r) * PS + 2 * t2);
        #pragma unroll
        for (int s = 0; s < 8; s++) nk[s] = lds2(pkb + (16 * s) * PS + 2 * t2);
        #pragma unroll
        for (int r = 0; r < 4; r++)
            #pragma unroll
            for (int s = 0; s < 8; s++) {
                u64t d2v = add2(pj[r], nk[s]);
                float lo, hi; unpack2(d2v, lo, hi);
                float tl = fabsf(lo) + cnr[r][s];
                float th = fabsf(hi) + cnr[r][s];
                tl = fmaxf(tl, 0.0f);
                th = fmaxf(th, 0.0f);
                hs2[s] = add2(hs2[s], pack2(tl, th));
            }
    }

    float hsum = 0.0f;
    #pragma unroll
    for (int s = 0; s < 8; s++) {
        float lo, hi; unpack2(hs2[s], lo, hi);
        hsum += lo + hi;
    }

    // ---- reduce + accumulate + epilogue ----
    #pragma unroll
    for (int o = 16; o > 0; o >>= 1) hsum += __shfl_xor_sync(0xffffffffu, hsum, o);
    if (lane == 0) s_red[wid] = hsum;
    __syncthreads();
    if (tid == 0) {
        float bs = 0.0f;
        #pragma unroll
        for (int w = 0; w < NTHR / 32; w++) bs += s_red[w];
        atomicAdd(&g_acc, (double)bs);
        __threadfence();
        int t = atomicAdd(&g_count, 1);
        s_last = (t == NBLK - 1);
    }
    __syncthreads();
    if (s_last && tid == 0) {
        double R  = g_acc;
        double mf = 2.0 * R / ((double)NROWS * (double)(NROWS - 1) * (double)NT);
        out[0] = fmaxf((float)mf - *target, 0.0f);
        g_acc = 0.0;
        g_count = 0;
    }
}

extern "C" void kernel_launch(void* const* d_in, const int* in_sizes, int n_in,
                              void* d_out, int out_size) {
    const float* target = (const float*)d_in[0];
    const float* pred   = (const float*)d_in[1];
    const float* X      = (const float*)d_in[2];
    const float* scale  = (const float*)d_in[4];
    float* out = (float*)d_out;

    cudaFuncSetAttribute(fused_kernel,
                         cudaFuncAttributeMaxDynamicSharedMemorySize, SMEM_BYTES);
    fused_kernel<<<NBLK, NTHR, SMEM_BYTES>>>(X, pred, scale, target, out);
}